// round 10
// baseline (speedup 1.0000x reference)
#include <cuda_runtime.h>
#include <cstdint>

#define HH 512
#define WW 512
#define CC 19
#define BB 4
#define NP (HH*WW)            // 262144 pixels per plane
#define NPRED (BB*CC)         // 76 pred planes (tgt planes are NPRED..2*NPRED-1)
#define NPL (2*NPRED)         // 152 planes total
#define TILE 32
#define HTILE 34
#define HTILE2 (HTILE*HTILE)  // 1156
// smem: S[19][34][34] floats + PM[34][34] words + 38 set counters + 38 merge counters
#define SMEM_BYTES (CC*HTILE2*4 + HTILE2*4 + 76*4)

#define PMASK 0x7FFFFu        // low 19 bits: pred mask
#define TSHIFT 19             // bits [19:24]: target class, 31 = ignore/invalid
#define INVALIDW (31u << TSHIFT)

#define NSEAM 15              // internal tile seams per direction
#define EDGES_PER_DIR (NSEAM*512)     // 7680
#define EDGES_PER_B   (2*EDGES_PER_DIR)

// ---------------- device scratch (static allocation: allowed) ----------------
__device__ int            g_labels[NPL*(size_t)NP];   // touched only at adjacency endpoints
__device__ unsigned int   g_pm[BB*(size_t)NP];        // packed words (written only on seam lines)
__device__ int            g_setcnt[NPL];
__device__ int            g_mergecnt[NPL];
__device__ int            g_n1;       // #(pred_b & valid)
__device__ int            g_n11;      // #(pred_b & tgt_b & valid)
__device__ int            g_nvalid;   // #valid pixels (B,H,W)
__device__ int            g_is64;     // target dtype flag

// ---------------- prolog: zero counters + dtype detect ----------------
__global__ void k_prolog(const int* __restrict__ traw) {
    __shared__ int bad;
    int t = threadIdx.x;
    if (t < NPL) { g_setcnt[t] = 0; g_mergecnt[t] = 0; }
    if (t == 0)  { g_n1 = 0; g_n11 = 0; g_nvalid = 0; bad = 0; }
    __syncthreads();
    int mybad = 0;
    #pragma unroll
    for (int k = 0; k < 32; k++) {
        int i = 2*(t + k*256) + 1;    // independent loads -> full MLP
        mybad |= traw[i];
    }
    if (__any_sync(0xffffffffu, mybad != 0))
        if ((t & 31) == 0) atomicOr(&bad, 1);
    __syncthreads();
    if (t == 0) g_is64 = !bad;
}

__device__ __forceinline__ int ldT(const void* t, int is64, size_t i) {
    long long v = is64 ? ((const long long*)t)[i] : (long long)((const int*)t)[i];
    return (v == 255) ? -1 : (int)v;    // -1 = ignore
}

// ---------------- union-find (4-connectivity, per-plane) ----------------
__device__ __forceinline__ int findRoot(int x) {
    int p = g_labels[x];
    while (p != x) {
        int gp = g_labels[p];
        if (gp != p) g_labels[x] = gp;   // path halving (parents strictly decrease; race-safe)
        x = p; p = gp;
    }
    return x;
}

// Returns 1 iff this call performed the CAS that merged two distinct trees.
__device__ __forceinline__ int unite(int a, int b) {
    while (true) {
        a = findRoot(a); b = findRoot(b);
        if (a == b) return 0;
        int mx = a > b ? a : b;
        int mn = a > b ? b : a;
        int old = atomicCAS(&g_labels[mx], mx, mn);
        if (old == mx) return 1;
        a = old; b = mn;
    }
}

// ------- fused softmax + boundary + counts + block-local label init + intra-tile unions -------
__global__ void __launch_bounds__(512)
k_fused(const float* __restrict__ pred, const void* __restrict__ targetv) {
    extern __shared__ float sm[];
    float*    S    = sm;                              // [CC][34][34] softmax (0 outside image)
    unsigned* PM   = (unsigned*)(sm + CC*HTILE2);     // [34][34] packed pm|class words
    int*      scnt = (int*)(PM + HTILE2);             // [38] per-plane set counts
    int*      mc   = scnt + 38;                       // [38] per-plane merge counts

    const int tx = threadIdx.x, ty = threadIdx.y;     // 32 x 16
    const int tid = ty*32 + tx;
    const int gx0 = blockIdx.x*TILE, gy0 = blockIdx.y*TILE;
    const int b = blockIdx.z;
    const int is64 = g_is64;

    if (tid < 38) { scnt[tid] = 0; mc[tid] = 0; }

    // --- halo pass: softmax + packed word per pixel ---
    for (int i = tid; i < HTILE2; i += 512) {
        int ly = i / HTILE, lx = i - ly*HTILE;
        int gy = gy0 + ly - 1, gx = gx0 + lx - 1;
        if ((unsigned)gy < HH && (unsigned)gx < WW) {
            const float* base = pred + ((size_t)b*CC)*NP + (size_t)gy*WW + gx;
            float v[CC];
            float mx = -1e30f;
            #pragma unroll
            for (int c = 0; c < CC; c++) { v[c] = base[(size_t)c*NP]; mx = fmaxf(mx, v[c]); }
            float s = 0.f;
            #pragma unroll
            for (int c = 0; c < CC; c++) { v[c] = __expf(v[c] - mx); s += v[c]; }
            float inv = 1.0f / s;
            unsigned pmb = 0u;
            #pragma unroll
            for (int c = 0; c < CC; c++) {
                float sc = v[c]*inv;
                S[c*HTILE2 + i] = sc;
                pmb |= ((unsigned)(sc > 0.5f)) << c;
            }
            int t = ldT(targetv, is64, (size_t)b*NP + (size_t)gy*WW + gx);
            unsigned cls;
            if (t >= 0) cls = (unsigned)t; else { cls = 31u; pmb = 0u; }
            PM[i] = pmb | (cls << TSHIFT);
        } else {
            #pragma unroll
            for (int c = 0; c < CC; c++) S[c*HTILE2 + i] = 0.f;
            PM[i] = INVALIDW;
        }
    }
    __syncthreads();

    // --- interior pass: 2 adjacent rows per thread ---
    const int row0 = 2*ty;                     // interior rows row0, row0+1
    const int gx = gx0 + tx;
    const int pix0 = (gy0 + row0)*WW + gx;
    const int pix1 = pix0 + WW;
    const int li0 = (row0+1)*HTILE + (tx+1);   // halo index of pixel0

    // 4x3 PM neighborhood (halo rows row0..row0+3, cols tx..tx+2)
    const unsigned m00=PM[li0-HTILE-1], m01=PM[li0-HTILE], m02=PM[li0-HTILE+1];
    const unsigned m10=PM[li0-1],       m11=PM[li0],       m12=PM[li0+1];
    const unsigned m20=PM[li0+HTILE-1], m21=PM[li0+HTILE], m22=PM[li0+HTILE+1];
    const unsigned m30=PM[li0+2*HTILE-1], m31=PM[li0+2*HTILE], m32=PM[li0+2*HTILE+1];

    const unsigned c0 = m11 >> TSHIFT, c1 = m21 >> TSHIFT;
    const bool v0 = c0 < CC, v1 = c1 < CC;

    // target boundary, all channels bit-parallel
    unsigned nbm0 = (1u<<(m00>>TSHIFT)) | (1u<<(m01>>TSHIFT)) | (1u<<(m02>>TSHIFT))
                  | (1u<<(m10>>TSHIFT)) | (1u<<(m12>>TSHIFT))
                  | (1u<<(m20>>TSHIFT)) | (1u<<(m21>>TSHIFT)) | (1u<<(m22>>TSHIFT));
    int t8_0 = ((m00>>TSHIFT)==c0)+((m01>>TSHIFT)==c0)+((m02>>TSHIFT)==c0)
             + ((m10>>TSHIFT)==c0)+((m12>>TSHIFT)==c0)
             + ((m20>>TSHIFT)==c0)+((m21>>TSHIFT)==c0)+((m22>>TSHIFT)==c0);
    unsigned tb0 = nbm0 & PMASK;
    if (v0) { if (t8_0 < 8) tb0 |= 1u<<c0; else tb0 &= ~(1u<<c0); }

    unsigned nbm1 = (1u<<(m10>>TSHIFT)) | (1u<<(m11>>TSHIFT)) | (1u<<(m12>>TSHIFT))
                  | (1u<<(m20>>TSHIFT)) | (1u<<(m22>>TSHIFT))
                  | (1u<<(m30>>TSHIFT)) | (1u<<(m31>>TSHIFT)) | (1u<<(m32>>TSHIFT));
    int t8_1 = ((m10>>TSHIFT)==c1)+((m11>>TSHIFT)==c1)+((m12>>TSHIFT)==c1)
             + ((m20>>TSHIFT)==c1)+((m22>>TSHIFT)==c1)
             + ((m30>>TSHIFT)==c1)+((m31>>TSHIFT)==c1)+((m32>>TSHIFT)==c1);
    unsigned tb1 = nbm1 & PMASK;
    if (v1) { if (t8_1 < 8) tb1 |= 1u<<c1; else tb1 &= ~(1u<<c1); }

    // pred boundary stencil, row-sum reuse across the 2 pixels
    unsigned pb0 = 0u, pb1 = 0u;
    const int sbase = row0*HTILE + tx;         // halo row row0, col tx
    #pragma unroll
    for (int c = 0; c < CC; c++) {
        const float* Sp = S + c*HTILE2 + sbase;
        float a0=Sp[0],        a1=Sp[1],          a2=Sp[2];
        float b0=Sp[HTILE],    b1=Sp[HTILE+1],    b2=Sp[HTILE+2];
        float d0=Sp[2*HTILE],  d1=Sp[2*HTILE+1],  d2=Sp[2*HTILE+2];
        float e0=Sp[3*HTILE],  e1=Sp[3*HTILE+1],  e2=Sp[3*HTILE+2];
        float HA=a0+a1+a2, HB=b0+b1+b2, HD=d0+d1+d2, HE=e0+e1+e2;
        float lap0 = 9.0f*b1 - (HA+HB+HD);
        float lap1 = 9.0f*d1 - (HB+HD+HE);
        pb0 |= ((unsigned)(fabsf(lap0) > 0.1f)) << c;
        pb1 |= ((unsigned)(fabsf(lap1) > 0.1f)) << c;
    }

    // scalar + per-plane counters
    int myN1 = 0, myN11 = 0, myV = 0;
    if (v0) { myV++; myN1 += __popc(pb0); myN11 += __popc(pb0 & tb0); atomicAdd(&scnt[19+c0], 1); }
    if (v1) { myV++; myN1 += __popc(pb1); myN11 += __popc(pb1 & tb1); atomicAdd(&scnt[19+c1], 1); }

    const unsigned pmb0 = m11 & PMASK, pmb1 = m21 & PMASK;
    unsigned t = pmb0;
    while (t) { int c = __ffs(t)-1; t &= t-1; atomicAdd(&scnt[c], 1); }
    t = pmb1;
    while (t) { int c = __ffs(t)-1; t &= t-1; atomicAdd(&scnt[c], 1); }

    // --- block-local label init: only OWN pixels, any-direction adjacency ---
    const int pbase = b*CC;
    unsigned ni = pmb0 & ((m01|m10|m12|m21) & PMASK);
    while (ni) { int c=__ffs(ni)-1; ni&=ni-1; int base=(pbase+c)*NP; g_labels[base+pix0]=base+pix0; }
    ni = pmb1 & ((m11|m20|m22|m31) & PMASK);
    while (ni) { int c=__ffs(ni)-1; ni&=ni-1; int base=(pbase+c)*NP; g_labels[base+pix1]=base+pix1; }
    if (v0) {
        if ((m01>>TSHIFT)==c0 || (m10>>TSHIFT)==c0 || (m12>>TSHIFT)==c0 || c1==c0) {
            int base = (NPRED+pbase+(int)c0)*NP; g_labels[base+pix0]=base+pix0;
        }
    }
    if (v1) {
        if (c0==c1 || (m20>>TSHIFT)==c1 || (m22>>TSHIFT)==c1 || (m31>>TSHIFT)==c1) {
            int base = (NPRED+pbase+(int)c1)*NP; g_labels[base+pix1]=base+pix1;
        }
    }

    // packed words out — only seam rows/cols are ever read downstream
    if (tx==0 || tx==31 || ty==0)  g_pm[(size_t)b*NP + pix0] = m11;
    if (tx==0 || tx==31 || ty==15) g_pm[(size_t)b*NP + pix1] = m21;

    __syncthreads();   // all inits in this tile complete

    // --- intra-tile unions (cross-tile edges deferred to k_seam) ---
    if (tx < 31) {
        unsigned u = pmb0 & m12;
        while (u) { int c=__ffs(u)-1; u&=u-1; int base=(pbase+c)*NP;
                    if (unite(base+pix0, base+pix0+1)) atomicAdd(&mc[c],1); }
        u = pmb1 & m22;
        while (u) { int c=__ffs(u)-1; u&=u-1; int base=(pbase+c)*NP;
                    if (unite(base+pix1, base+pix1+1)) atomicAdd(&mc[c],1); }
    }
    {
        unsigned u = pmb0 & pmb1;
        while (u) { int c=__ffs(u)-1; u&=u-1; int base=(pbase+c)*NP;
                    if (unite(base+pix0, base+pix1)) atomicAdd(&mc[c],1); }
    }
    if (ty < 15) {
        unsigned u = pmb1 & (m31 & PMASK);
        while (u) { int c=__ffs(u)-1; u&=u-1; int base=(pbase+c)*NP;
                    if (unite(base+pix1, base+pix1+WW)) atomicAdd(&mc[c],1); }
    }
    if (v0) {
        if (tx < 31 && c0 == (m12>>TSHIFT)) {
            int base=(NPRED+pbase+(int)c0)*NP;
            if (unite(base+pix0, base+pix0+1)) atomicAdd(&mc[19+c0],1);
        }
        if (c0 == c1) {
            int base=(NPRED+pbase+(int)c0)*NP;
            if (unite(base+pix0, base+pix1)) atomicAdd(&mc[19+c0],1);
        }
    }
    if (v1) {
        if (tx < 31 && c1 == (m22>>TSHIFT)) {
            int base=(NPRED+pbase+(int)c1)*NP;
            if (unite(base+pix1, base+pix1+1)) atomicAdd(&mc[19+c1],1);
        }
        if (ty < 15 && c1 == (m31>>TSHIFT)) {
            int base=(NPRED+pbase+(int)c1)*NP;
            if (unite(base+pix1, base+pix1+WW)) atomicAdd(&mc[19+c1],1);
        }
    }

    // warp-reduce scalar counters
    #pragma unroll
    for (int o = 16; o > 0; o >>= 1) {
        myN1  += __shfl_down_sync(0xffffffffu, myN1,  o);
        myN11 += __shfl_down_sync(0xffffffffu, myN11, o);
        myV   += __shfl_down_sync(0xffffffffu, myV,   o);
    }
    if (tx == 0) {
        if (myN1)  atomicAdd(&g_n1,  myN1);
        if (myN11) atomicAdd(&g_n11, myN11);
        if (myV)   atomicAdd(&g_nvalid, myV);
    }
    __syncthreads();
    if (tid < 19) {
        int u0 = scnt[tid], u1 = scnt[19 + tid];
        if (u0) atomicAdd(&g_setcnt[b*CC + tid],         u0);
        if (u1) atomicAdd(&g_setcnt[NPRED + b*CC + tid], u1);
        int w0 = mc[tid], w1 = mc[19 + tid];
        if (w0) atomicAdd(&g_mergecnt[b*CC + tid],         w0);
        if (w1) atomicAdd(&g_mergecnt[NPRED + b*CC + tid], w1);
    }
}

// ---------------- seam unions: cross-tile edges only ----------------
__global__ void __launch_bounds__(256) k_seam() {
    __shared__ int smc[38];
    const int tid = threadIdx.x;
    if (tid < 38) smc[tid] = 0;
    __syncthreads();

    const int b = blockIdx.y;
    const int eid = blockIdx.x*256 + tid;
    const unsigned* pmp = g_pm + (size_t)b*NP;

    int pix, other;
    if (eid < EDGES_PER_DIR) {               // vertical seam: (x,y)->(x+1,y), x=32s+31
        int s = eid >> 9, y = eid & 511;
        pix = y*WW + (s*32 + 31); other = pix + 1;
    } else {                                  // horizontal seam: (x,y)->(x,y+1), y=32s+31
        int e2 = eid - EDGES_PER_DIR;
        int s = e2 >> 9, x = e2 & 511;
        pix = (s*32 + 31)*WW + x; other = pix + WW;
    }

    const unsigned w = pmp[pix], w2 = pmp[other];
    const int pbase = b*CC;
    unsigned a = w & w2 & PMASK;
    while (a) {
        int c = __ffs(a)-1; a &= a-1;
        int base = (pbase+c)*NP;
        if (unite(base+pix, base+other)) atomicAdd(&smc[c], 1);
    }
    const unsigned tc = w >> TSHIFT;
    if (tc < CC && tc == (w2 >> TSHIFT)) {
        int base = (NPRED+pbase+(int)tc)*NP;
        if (unite(base+pix, base+other)) atomicAdd(&smc[19+tc], 1);
    }
    __syncthreads();
    if (tid < 19) {
        if (smc[tid])     atomicAdd(&g_mergecnt[pbase+tid],           smc[tid]);
        if (smc[19+tid])  atomicAdd(&g_mergecnt[NPRED+pbase+tid],     smc[19+tid]);
    }
}

// ---------------- final combine ----------------
__global__ void k_final(float* __restrict__ out) {
    __shared__ float red[128];
    int t = threadIdx.x;
    float conn = 0.f;
    if (t < NPRED) {
        int cp = g_setcnt[t]         - g_mergecnt[t];           // pred components
        int ct = g_setcnt[NPRED + t] - g_mergecnt[NPRED + t];   // tgt components
        if (g_setcnt[NPRED + t] > 0) conn = fabsf((float)(cp - ct));
    }
    red[t] = conn;
    __syncthreads();
    for (int o = 64; o > 0; o >>= 1) { if (t < o) red[t] += red[t + o]; __syncthreads(); }
    if (t == 0) {
        const double LN2 = 0.6931471805599453;
        const double S1  = 0.3132616875182228;   // log1p(exp(-1))
        double n1 = (double)g_n1, n11 = (double)g_n11, nv = (double)g_nvalid;
        double Ntot = (double)BB*CC*HH*WW;
        // per-pixel BCE: x=0 -> ln2 ; x=1,y=0 -> 1+S1 ; x=1,y=1 -> S1
        double bsum = (Ntot - n1)*LN2 + n1*(1.0 + S1) - n11;
        double bl = bsum / (nv + 1e-8);
        double cl = (double)red[0] / ((double)(BB*CC) + 1e-8);
        out[0] = (float)(bl + 0.1*cl);
    }
}

// ---------------- launch ----------------
extern "C" void kernel_launch(void* const* d_in, const int* in_sizes, int n_in,
                              void* d_out, int out_size) {
    // Robust input selection: pred is the large float buffer (B*C*H*W elems).
    int pi = 0, ti = 1;
    if (n_in >= 2 && in_sizes[1] == BB*CC*NP && in_sizes[0] != BB*CC*NP) { pi = 1; ti = 0; }
    const float* pred = (const float*)d_in[pi];
    const void*  targ = d_in[ti];
    float* out = (float*)d_out;

    cudaFuncSetAttribute(k_fused, cudaFuncAttributeMaxDynamicSharedMemorySize, SMEM_BYTES);

    k_prolog<<<1, 256>>>((const int*)targ);
    dim3 g1(WW/TILE, HH/TILE, BB), b1(32, 16);
    k_fused<<<g1, b1, SMEM_BYTES>>>(pred, targ);
    k_seam<<<dim3(EDGES_PER_B/256, BB), 256>>>();
    k_final<<<1, 128>>>(out);
}

// round 12
// speedup vs baseline: 1.3219x; 1.3219x over previous
#include <cuda_runtime.h>
#include <cstdint>

#define HH 512
#define WW 512
#define CC 19
#define BB 4
#define NP (HH*WW)            // 262144 pixels per plane
#define NPRED (BB*CC)         // 76 pred planes (tgt planes are NPRED..2*NPRED-1)
#define NPL (2*NPRED)         // 152 planes total
#define TILE 32
#define HTILE 34
#define HTILE2 (HTILE*HTILE)  // 1156
// smem: S[19][34][34] floats + PM[34][34] words + 38 counters + flag
#define SMEM_BYTES (CC*HTILE2*4 + HTILE2*4 + 40*4)

#define PMASK 0x7FFFFu        // low 19 bits: pred mask
#define TSHIFT 19             // bits [19:24]: target class, 31 = ignore/invalid
#define INVALIDW (31u << TSHIFT)

// ---------------- device scratch (static allocation: allowed) ----------------
// NOTE: counters below are zero at module load and re-zeroed by k_final at the
// end of every run, so no init kernel is needed (graph-replay safe).
__device__ int            g_labels[NPL*(size_t)NP];   // touched only at adjacency endpoints
__device__ unsigned int   g_pm[BB*(size_t)NP];        // packed pred mask + target class (4 MB)
__device__ int            g_setcnt[NPL];
__device__ int            g_mergecnt[NPL];
__device__ int            g_n1;       // #(pred_b & valid)
__device__ int            g_n11;      // #(pred_b & tgt_b & valid)
__device__ int            g_nvalid;   // #valid pixels (B,H,W)

__device__ __forceinline__ int ldT(const void* t, int is64, size_t i) {
    long long v = is64 ? ((const long long*)t)[i] : (long long)((const int*)t)[i];
    return (v == 255) ? -1 : (int)v;    // -1 = ignore
}

// ---------------- fused softmax + boundary + packed masks + sparse label init ----------------
__global__ void __launch_bounds__(512)
k_fused(const float* __restrict__ pred, const void* __restrict__ targetv) {
    extern __shared__ float sm[];
    float*    S    = sm;                              // [CC][34][34] softmax (0 outside image)
    unsigned* PM   = (unsigned*)(sm + CC*HTILE2);     // [34][34] packed pm|class words
    int*      scnt = (int*)(PM + HTILE2);             // [38] per-plane set counts
    int*      sflag = scnt + 38;                      // [1] is64 flag

    const int tx = threadIdx.x, ty = threadIdx.y;     // 32 x 16
    const int tid = ty*32 + tx;
    const int gx0 = blockIdx.x*TILE, gy0 = blockIdx.y*TILE;
    const int b = blockIdx.z;

    if (tid < 38) scnt[tid] = 0;

    // inline dtype detect: int64 target => high words of first 64 pairs all zero.
    // (int32 class data 0..18 reinterpreted: odd words nonzero-anywhere w.p. 1-(1/19)^64)
    if (tid < 32) {
        const int* traw = (const int*)targetv;
        int r = traw[2*tid + 1] | traw[2*(tid + 32) + 1];
        unsigned bal = __ballot_sync(0xffffffffu, r != 0);
        if (tid == 0) sflag[0] = (bal == 0u);
    }
    __syncthreads();
    const int is64 = sflag[0];

    // --- halo pass: softmax + packed word per pixel ---
    for (int i = tid; i < HTILE2; i += 512) {
        int ly = i / HTILE, lx = i - ly*HTILE;
        int gy = gy0 + ly - 1, gx = gx0 + lx - 1;
        if ((unsigned)gy < HH && (unsigned)gx < WW) {
            const float* base = pred + ((size_t)b*CC)*NP + (size_t)gy*WW + gx;
            float v[CC];
            float mx = -1e30f;
            #pragma unroll
            for (int c = 0; c < CC; c++) { v[c] = base[(size_t)c*NP]; mx = fmaxf(mx, v[c]); }
            float s = 0.f;
            #pragma unroll
            for (int c = 0; c < CC; c++) { v[c] = __expf(v[c] - mx); s += v[c]; }
            float inv = 1.0f / s;
            unsigned pmb = 0u;
            #pragma unroll
            for (int c = 0; c < CC; c++) {
                float sc = v[c]*inv;
                S[c*HTILE2 + i] = sc;
                pmb |= ((unsigned)(sc > 0.5f)) << c;
            }
            int t = ldT(targetv, is64, (size_t)b*NP + (size_t)gy*WW + gx);
            unsigned cls;
            if (t >= 0) cls = (unsigned)t; else { cls = 31u; pmb = 0u; }
            PM[i] = pmb | (cls << TSHIFT);
        } else {
            #pragma unroll
            for (int c = 0; c < CC; c++) S[c*HTILE2 + i] = 0.f;
            PM[i] = INVALIDW;
        }
    }
    __syncthreads();

    // --- interior pass: 2 adjacent rows per thread ---
    const int row0 = 2*ty;                     // interior rows row0, row0+1
    const int gx = gx0 + tx;
    const int pix0 = (gy0 + row0)*WW + gx;
    const int pix1 = pix0 + WW;
    const int li0 = (row0+1)*HTILE + (tx+1);   // halo index of pixel0

    // 4x3 PM neighborhood (halo rows row0..row0+3, cols tx..tx+2)
    const unsigned m00=PM[li0-HTILE-1], m01=PM[li0-HTILE], m02=PM[li0-HTILE+1];
    const unsigned m10=PM[li0-1],       m11=PM[li0],       m12=PM[li0+1];
    const unsigned m20=PM[li0+HTILE-1], m21=PM[li0+HTILE], m22=PM[li0+HTILE+1];
    const unsigned m30=PM[li0+2*HTILE-1], m31=PM[li0+2*HTILE], m32=PM[li0+2*HTILE+1];

    const unsigned c0 = m11 >> TSHIFT, c1 = m21 >> TSHIFT;
    const bool v0 = c0 < CC, v1 = c1 < CC;

    // target boundary, all channels bit-parallel
    unsigned nbm0 = (1u<<(m00>>TSHIFT)) | (1u<<(m01>>TSHIFT)) | (1u<<(m02>>TSHIFT))
                  | (1u<<(m10>>TSHIFT)) | (1u<<(m12>>TSHIFT))
                  | (1u<<(m20>>TSHIFT)) | (1u<<(m21>>TSHIFT)) | (1u<<(m22>>TSHIFT));
    int t8_0 = ((m00>>TSHIFT)==c0)+((m01>>TSHIFT)==c0)+((m02>>TSHIFT)==c0)
             + ((m10>>TSHIFT)==c0)+((m12>>TSHIFT)==c0)
             + ((m20>>TSHIFT)==c0)+((m21>>TSHIFT)==c0)+((m22>>TSHIFT)==c0);
    unsigned tb0 = nbm0 & PMASK;
    if (v0) { if (t8_0 < 8) tb0 |= 1u<<c0; else tb0 &= ~(1u<<c0); }

    unsigned nbm1 = (1u<<(m10>>TSHIFT)) | (1u<<(m11>>TSHIFT)) | (1u<<(m12>>TSHIFT))
                  | (1u<<(m20>>TSHIFT)) | (1u<<(m22>>TSHIFT))
                  | (1u<<(m30>>TSHIFT)) | (1u<<(m31>>TSHIFT)) | (1u<<(m32>>TSHIFT));
    int t8_1 = ((m10>>TSHIFT)==c1)+((m11>>TSHIFT)==c1)+((m12>>TSHIFT)==c1)
             + ((m20>>TSHIFT)==c1)+((m22>>TSHIFT)==c1)
             + ((m30>>TSHIFT)==c1)+((m31>>TSHIFT)==c1)+((m32>>TSHIFT)==c1);
    unsigned tb1 = nbm1 & PMASK;
    if (v1) { if (t8_1 < 8) tb1 |= 1u<<c1; else tb1 &= ~(1u<<c1); }

    // pred boundary stencil, row-sum reuse across the 2 pixels
    unsigned pb0 = 0u, pb1 = 0u;
    const int sbase = row0*HTILE + tx;         // halo row row0, col tx
    #pragma unroll
    for (int c = 0; c < CC; c++) {
        const float* Sp = S + c*HTILE2 + sbase;
        float a0=Sp[0],        a1=Sp[1],          a2=Sp[2];
        float b0=Sp[HTILE],    b1=Sp[HTILE+1],    b2=Sp[HTILE+2];
        float d0=Sp[2*HTILE],  d1=Sp[2*HTILE+1],  d2=Sp[2*HTILE+2];
        float e0=Sp[3*HTILE],  e1=Sp[3*HTILE+1],  e2=Sp[3*HTILE+2];
        float HA=a0+a1+a2, HB=b0+b1+b2, HD=d0+d1+d2, HE=e0+e1+e2;
        float lap0 = 9.0f*b1 - (HA+HB+HD);
        float lap1 = 9.0f*d1 - (HB+HD+HE);
        pb0 |= ((unsigned)(fabsf(lap0) > 0.1f)) << c;
        pb1 |= ((unsigned)(fabsf(lap1) > 0.1f)) << c;
    }

    // counters
    int myN1 = 0, myN11 = 0, myV = 0;
    if (v0) { myV++; myN1 += __popc(pb0); myN11 += __popc(pb0 & tb0); atomicAdd(&scnt[19+c0], 1); }
    if (v1) { myV++; myN1 += __popc(pb1); myN11 += __popc(pb1 & tb1); atomicAdd(&scnt[19+c1], 1); }

    const unsigned pmb0 = m11 & PMASK, pmb1 = m21 & PMASK;
    // pred set counts (sparse)
    unsigned t = pmb0;
    while (t) { int c = __ffs(t)-1; t &= t-1; atomicAdd(&scnt[c], 1); }
    t = pmb1;
    while (t) { int c = __ffs(t)-1; t &= t-1; atomicAdd(&scnt[c], 1); }

    // sparse label init (adjacency endpoints only); identity writes are race-safe
    const int pbase = b*CC;
    unsigned aE = pmb0 & m12;
    while (aE) { int c=__ffs(aE)-1; aE&=aE-1; int base=(pbase+c)*NP;
                 g_labels[base+pix0]=base+pix0; g_labels[base+pix0+1]=base+pix0+1; }
    unsigned aS = pmb0 & m21;
    while (aS) { int c=__ffs(aS)-1; aS&=aS-1; int base=(pbase+c)*NP;
                 g_labels[base+pix0]=base+pix0; g_labels[base+pix1]=base+pix1; }
    aE = pmb1 & m22;
    while (aE) { int c=__ffs(aE)-1; aE&=aE-1; int base=(pbase+c)*NP;
                 g_labels[base+pix1]=base+pix1; g_labels[base+pix1+1]=base+pix1+1; }
    aS = pmb1 & m31;
    while (aS) { int c=__ffs(aS)-1; aS&=aS-1; int base=(pbase+c)*NP;
                 g_labels[base+pix1]=base+pix1; g_labels[base+pix1+WW]=base+pix1+WW; }

    if (v0) {
        int base = (NPRED + pbase + (int)c0)*NP;
        if (c0 == (m12>>TSHIFT)) { g_labels[base+pix0]=base+pix0; g_labels[base+pix0+1]=base+pix0+1; }
        if (c0 == (m21>>TSHIFT)) { g_labels[base+pix0]=base+pix0; g_labels[base+pix1]=base+pix1; }
    }
    if (v1) {
        int base = (NPRED + pbase + (int)c1)*NP;
        if (c1 == (m22>>TSHIFT)) { g_labels[base+pix1]=base+pix1; g_labels[base+pix1+1]=base+pix1+1; }
        if (c1 == (m31>>TSHIFT)) { g_labels[base+pix1]=base+pix1; g_labels[base+pix1+WW]=base+pix1+WW; }
    }

    // packed words out (coalesced per warp)
    g_pm[(size_t)b*NP + pix0] = m11;
    g_pm[(size_t)b*NP + pix1] = m21;

    // warp-reduce scalar counters
    #pragma unroll
    for (int o = 16; o > 0; o >>= 1) {
        myN1  += __shfl_down_sync(0xffffffffu, myN1,  o);
        myN11 += __shfl_down_sync(0xffffffffu, myN11, o);
        myV   += __shfl_down_sync(0xffffffffu, myV,   o);
    }
    if (tx == 0) {
        if (myN1)  atomicAdd(&g_n1,  myN1);
        if (myN11) atomicAdd(&g_n11, myN11);
        if (myV)   atomicAdd(&g_nvalid, myV);
    }
    __syncthreads();
    if (tid < 19) {
        int u0 = scnt[tid], u1 = scnt[19 + tid];
        if (u0) atomicAdd(&g_setcnt[b*CC + tid],         u0);
        if (u1) atomicAdd(&g_setcnt[NPRED + b*CC + tid], u1);
    }
}

// ---------------- union-find (4-connectivity, per-plane) ----------------
__device__ __forceinline__ int findRoot(int x) {
    int p = g_labels[x];
    while (p != x) {
        int gp = g_labels[p];
        if (gp != p) g_labels[x] = gp;   // path halving (parents strictly decrease; race-safe)
        x = p; p = gp;
    }
    return x;
}

// Returns 1 iff this call performed the CAS that merged two distinct trees.
__device__ __forceinline__ int unite(int a, int b) {
    while (true) {
        a = findRoot(a); b = findRoot(b);
        if (a == b) return 0;
        int mx = a > b ? a : b;
        int mn = a > b ? b : a;
        int old = atomicCAS(&g_labels[mx], mx, mn);
        if (old == mx) return 1;
        a = old; b = mn;
    }
}

// ---------------- edge detection + union: 1 thread/pixel, smem merge counters ----------------
__global__ void __launch_bounds__(256) k_unite() {
    __shared__ int smc[38];
    const int tid = threadIdx.x;
    if (tid < 38) smc[tid] = 0;
    __syncthreads();

    const int b = blockIdx.y;
    const int pix = blockIdx.x*256 + tid;
    const int x = pix & (WW-1), y = pix >> 9;
    const unsigned* pmp = g_pm + (size_t)b*NP;

    const unsigned w  = pmp[pix];
    const unsigned wE = (x < WW-1) ? pmp[pix+1]  : INVALIDW;
    const unsigned wS = (y < HH-1) ? pmp[pix+WW] : INVALIDW;

    const int pbase = b*CC;
    unsigned aE = w & wE & PMASK;
    while (aE) {
        int c = __ffs(aE)-1; aE &= aE-1;
        int base = (pbase+c)*NP;
        if (unite(base+pix, base+pix+1)) atomicAdd(&smc[c], 1);
    }
    unsigned aS = w & wS & PMASK;
    while (aS) {
        int c = __ffs(aS)-1; aS &= aS-1;
        int base = (pbase+c)*NP;
        if (unite(base+pix, base+pix+WW)) atomicAdd(&smc[c], 1);
    }
    const unsigned tc = w >> TSHIFT;
    if (tc < CC) {
        if (tc == (wE>>TSHIFT)) {
            int base = (NPRED+pbase+(int)tc)*NP;
            if (unite(base+pix, base+pix+1)) atomicAdd(&smc[19+tc], 1);
        }
        if (tc == (wS>>TSHIFT)) {
            int base = (NPRED+pbase+(int)tc)*NP;
            if (unite(base+pix, base+pix+WW)) atomicAdd(&smc[19+tc], 1);
        }
    }
    __syncthreads();
    if (tid < 19) {
        if (smc[tid])    atomicAdd(&g_mergecnt[pbase+tid], smc[tid]);
    } else if (tid < 38) {
        if (smc[tid])    atomicAdd(&g_mergecnt[NPRED+pbase+tid-19], smc[tid]);
    }
}

// ---------------- final combine + counter reset (replaces init kernel) ----------------
__global__ void k_final(float* __restrict__ out) {
    __shared__ float red[128];
    int t = threadIdx.x;
    float conn = 0.f;
    if (t < NPRED) {
        int cp = g_setcnt[t]         - g_mergecnt[t];           // pred components
        int ct = g_setcnt[NPRED + t] - g_mergecnt[NPRED + t];   // tgt components
        if (g_setcnt[NPRED + t] > 0) conn = fabsf((float)(cp - ct));
    }
    red[t] = conn;
    __syncthreads();
    for (int o = 64; o > 0; o >>= 1) { if (t < o) red[t] += red[t + o]; __syncthreads(); }
    if (t == 0) {
        const double LN2 = 0.6931471805599453;
        const double S1  = 0.3132616875182228;   // log1p(exp(-1))
        double n1 = (double)g_n1, n11 = (double)g_n11, nv = (double)g_nvalid;
        double Ntot = (double)BB*CC*HH*WW;
        // per-pixel BCE: x=0 -> ln2 ; x=1,y=0 -> 1+S1 ; x=1,y=1 -> S1
        double bsum = (Ntot - n1)*LN2 + n1*(1.0 + S1) - n11;
        double bl = bsum / (nv + 1e-8);
        double cl = (double)red[0] / ((double)(BB*CC) + 1e-8);
        out[0] = (float)(bl + 0.1*cl);
    }
    __syncthreads();   // all reads of counters complete before reset
    for (int i = t; i < NPL; i += 128) { g_setcnt[i] = 0; g_mergecnt[i] = 0; }
    if (t == 0) { g_n1 = 0; g_n11 = 0; g_nvalid = 0; }
}

// ---------------- launch (3 graph nodes) ----------------
extern "C" void kernel_launch(void* const* d_in, const int* in_sizes, int n_in,
                              void* d_out, int out_size) {
    // Robust input selection: pred is the large float buffer (B*C*H*W elems).
    int pi = 0, ti = 1;
    if (n_in >= 2 && in_sizes[1] == BB*CC*NP && in_sizes[0] != BB*CC*NP) { pi = 1; ti = 0; }
    const float* pred = (const float*)d_in[pi];
    const void*  targ = d_in[ti];
    float* out = (float*)d_out;

    cudaFuncSetAttribute(k_fused, cudaFuncAttributeMaxDynamicSharedMemorySize, SMEM_BYTES);

    dim3 g1(WW/TILE, HH/TILE, BB), b1(32, 16);
    k_fused<<<g1, b1, SMEM_BYTES>>>(pred, targ);
    k_unite<<<dim3(NP/256, BB), 256>>>();
    k_final<<<1, 128>>>(out);
}